// round 4
// baseline (speedup 1.0000x reference)
#include <cuda_runtime.h>
#include <cuda_bf16.h>
#include <cstdint>

// ---------------------------------------------------------------------------
// WordGraphNet: 2-layer weighted GraphConv, CSR pull-side aggregation.
//   layer(h,W,b): Wh = h@W + b ; s = segsum(Wh[src]*ew, dst) ; out = s/max(deg,1)
//   out = layer2( leaky_relu(layer1(x)) )
// ---------------------------------------------------------------------------

#define MAX_NODES 50000
#define MAX_EDGES 1200000
#define HID 64
#define NEG_SLOPE 0.01f
#define SCAN_T 1024

typedef unsigned long long ull;

__device__ float g_Wh[MAX_NODES * HID];
__device__ float g_h1[MAX_NODES * HID];
__device__ int   g_cnt[MAX_NODES];
__device__ int   g_off[MAX_NODES + 1];
__device__ int   g_cursor[MAX_NODES];
__device__ int2  g_csr[MAX_EDGES];

__device__ __forceinline__ float leaky(float v) {
    return v > 0.f ? v : NEG_SLOPE * v;
}

// ---- packed f32x2 helpers (Blackwell FFMA2) ----
__device__ __forceinline__ ull pack2dup(float v) {
    ull r; asm("mov.b64 %0, {%1, %1};" : "=l"(r) : "f"(v)); return r;
}
__device__ __forceinline__ void unpack2(ull v, float& lo, float& hi) {
    asm("mov.b64 {%0, %1}, %2;" : "=f"(lo), "=f"(hi) : "l"(v));
}
__device__ __forceinline__ ull fma2(ull a, ull b, ull c) {
    ull d; asm("fma.rn.f32x2 %0, %1, %2, %3;" : "=l"(d) : "l"(a), "l"(b), "l"(c));
    return d;
}

// ---------------------------------------------------------------------------
// CSR build
// ---------------------------------------------------------------------------
__global__ void hist_kernel(const int* __restrict__ dst, int* __restrict__ cnt,
                            int n_edges) {
    int e = blockIdx.x * blockDim.x + threadIdx.x;
    if (e < n_edges) atomicAdd(cnt + __ldg(dst + e), 1);
}

__global__ __launch_bounds__(SCAN_T)
void scan_kernel(const int* __restrict__ cnt, int* __restrict__ off,
                 int* __restrict__ cursor, int n) {
    __shared__ int sums[SCAN_T];
    int t = threadIdx.x;
    int ch = (n + SCAN_T - 1) / SCAN_T;
    int begin = min(t * ch, n);
    int end   = min(begin + ch, n);

    int s = 0;
    for (int i = begin; i < end; i++) s += __ldg(cnt + i);
    sums[t] = s;
    __syncthreads();

    for (int d = 1; d < SCAN_T; d <<= 1) {
        int v = (t >= d) ? sums[t - d] : 0;
        __syncthreads();
        sums[t] += v;
        __syncthreads();
    }

    int run = (t == 0) ? 0 : sums[t - 1];
    for (int i = begin; i < end; i++) {
        off[i] = run;
        cursor[i] = run;
        run += __ldg(cnt + i);
    }
    if (t == SCAN_T - 1) off[n] = sums[SCAN_T - 1];
}

__global__ void fill_kernel(const int* __restrict__ src, const int* __restrict__ dst,
                            const float* __restrict__ ew, int* __restrict__ cursor,
                            int2* __restrict__ csr, int n_edges) {
    int e = blockIdx.x * blockDim.x + threadIdx.x;
    if (e >= n_edges) return;
    int d = __ldg(dst + e);
    int pos = atomicAdd(cursor + d, 1);
    csr[pos] = make_int2(__ldg(src + e), __float_as_int(__ldg(ew + e)));
}

// ---------------------------------------------------------------------------
// Tiled GEMM + bias, f32x2 inner product.
// 128 threads, tile 128 nodes x 64 cols, 8 nodes x 8 cols per thread
// (cols held as 4 packed f32x2 accumulators per node).
// ---------------------------------------------------------------------------
#define TILE_M 128
#define KC 32
#define KCP 36

template <int K>
__global__ __launch_bounds__(128)
void gemm_tile_kernel(const float* __restrict__ H,
                      const float* __restrict__ Wg,
                      const float* __restrict__ bg,
                      float* __restrict__ out,
                      int n_nodes) {
    __shared__ float Hs[TILE_M * KCP];
    __shared__ float Ws[KC * HID];

    const int tid = threadIdx.x;
    const int tx = tid & 7;    // col group: [4tx..4tx+3] and [32+4tx..32+4tx+3]
    const int ty = tid >> 3;   // node group: ty + 16*i
    const int node0 = blockIdx.x * TILE_M;

    ull acc2[8][4];
#pragma unroll
    for (int i = 0; i < 8; i++)
#pragma unroll
        for (int j = 0; j < 4; j++) acc2[i][j] = 0ull;

    for (int kc0 = 0; kc0 < K; kc0 += KC) {
        {
            const float4* Wg4 = reinterpret_cast<const float4*>(Wg + kc0 * HID);
            float4* Ws4w = reinterpret_cast<float4*>(Ws);
#pragma unroll
            for (int f = tid; f < KC * 16; f += 128)
                Ws4w[f] = __ldg(Wg4 + f);
        }
#pragma unroll
        for (int f = tid; f < TILE_M * (KC / 4); f += 128) {
            int m = f >> 3;
            int j = f & 7;
            int node = node0 + m;
            float4 v = make_float4(0.f, 0.f, 0.f, 0.f);
            if (node < n_nodes)
                v = __ldg(reinterpret_cast<const float4*>(H + (size_t)node * K + kc0) + j);
            *reinterpret_cast<float4*>(Hs + m * KCP + 4 * j) = v;
        }
        __syncthreads();

        const ull* Ws2 = reinterpret_cast<const ull*>(Ws);
#pragma unroll 4
        for (int kk = 0; kk < KC; kk++) {
            ull w2[4];
            w2[0] = Ws2[kk * 32 + 2 * tx];
            w2[1] = Ws2[kk * 32 + 2 * tx + 1];
            w2[2] = Ws2[kk * 32 + 16 + 2 * tx];
            w2[3] = Ws2[kk * 32 + 16 + 2 * tx + 1];
#pragma unroll
            for (int i = 0; i < 8; i++) {
                ull h2 = pack2dup(Hs[(ty + 16 * i) * KCP + kk]);
#pragma unroll
                for (int j = 0; j < 4; j++)
                    acc2[i][j] = fma2(h2, w2[j], acc2[i][j]);
            }
        }
        __syncthreads();
    }

    float4 b0 = __ldg(reinterpret_cast<const float4*>(bg) + tx);
    float4 b1 = __ldg(reinterpret_cast<const float4*>(bg) + 8 + tx);
#pragma unroll
    for (int i = 0; i < 8; i++) {
        int node = node0 + ty + 16 * i;
        if (node < n_nodes) {
            float4 o0, o1;
            unpack2(acc2[i][0], o0.x, o0.y);
            unpack2(acc2[i][1], o0.z, o0.w);
            unpack2(acc2[i][2], o1.x, o1.y);
            unpack2(acc2[i][3], o1.z, o1.w);
            o0.x += b0.x; o0.y += b0.y; o0.z += b0.z; o0.w += b0.w;
            o1.x += b1.x; o1.y += b1.y; o1.z += b1.z; o1.w += b1.w;
            *reinterpret_cast<float4*>(out + (size_t)node * HID + tx * 4) = o0;
            *reinterpret_cast<float4*>(out + (size_t)node * HID + 32 + tx * 4) = o1;
        }
    }
}

// ---------------------------------------------------------------------------
// Pull-side aggregate with lane-cooperative CSR loads.
// 16 lanes per node; lane c4 owns float4 chunk c4 of the 64-wide row.
// Each round: 16 csr entries loaded coalesced (one per lane), broadcast via
// shfl(width=16), gathers issued with unroll-8 MLP. No address chaining.
// ---------------------------------------------------------------------------
template <bool DO_LEAKY>
__global__ __launch_bounds__(256)
void aggregate_kernel(const float4* __restrict__ Wh4,
                      const int2* __restrict__ csr,
                      const int* __restrict__ off,
                      float* __restrict__ out,
                      int n_nodes) {
    int gid = blockIdx.x * blockDim.x + threadIdx.x;
    int node = gid >> 4;
    int c4 = gid & 15;
    if (node >= n_nodes) return;

    int e   = __ldg(off + node);
    int end = __ldg(off + node + 1);
    float deg = (float)(end - e);

    float4 acc = make_float4(0.f, 0.f, 0.f, 0.f);

    // full 16-edge rounds
    for (; e + 16 <= end; e += 16) {
        int2 my = __ldg(csr + e + c4);
#pragma unroll 8
        for (int j = 0; j < 16; j++) {
            int sx = __shfl_sync(0xffffffffu, my.x, j, 16);
            int wy = __shfl_sync(0xffffffffu, my.y, j, 16);
            float w = __int_as_float(wy);
            float4 v = __ldg(Wh4 + (size_t)sx * 16 + c4);
            acc.x += v.x * w; acc.y += v.y * w;
            acc.z += v.z * w; acc.w += v.w * w;
        }
    }
    // tail (< 16 edges)
    int rem = end - e;
    if (rem > 0) {
        int2 my = (c4 < rem) ? __ldg(csr + e + c4) : make_int2(0, 0);
#pragma unroll 4
        for (int j = 0; j < rem; j++) {
            int sx = __shfl_sync(0xffffffffu, my.x, j, 16);
            int wy = __shfl_sync(0xffffffffu, my.y, j, 16);
            float w = __int_as_float(wy);
            float4 v = __ldg(Wh4 + (size_t)sx * 16 + c4);
            acc.x += v.x * w; acc.y += v.y * w;
            acc.z += v.z * w; acc.w += v.w * w;
        }
    }

    float inv = 1.0f / fmaxf(deg, 1.0f);
    acc.x *= inv; acc.y *= inv; acc.z *= inv; acc.w *= inv;
    if (DO_LEAKY) {
        acc.x = leaky(acc.x); acc.y = leaky(acc.y);
        acc.z = leaky(acc.z); acc.w = leaky(acc.w);
    }
    reinterpret_cast<float4*>(out)[gid] = acc;
}

// ---------------------------------------------------------------------------
// Launch
// ---------------------------------------------------------------------------
extern "C" void kernel_launch(void* const* d_in, const int* in_sizes, int n_in,
                              void* d_out, int out_size) {
    const float* x   = (const float*)d_in[0];
    const float* ew  = (const float*)d_in[1];
    const float* W1  = (const float*)d_in[2];
    const float* b1  = (const float*)d_in[3];
    const float* W2  = (const float*)d_in[4];
    const float* b2  = (const float*)d_in[5];
    const int*   src = (const int*)d_in[6];
    const int*   dst = (const int*)d_in[7];
    float*       out = (float*)d_out;

    int n_nodes = in_sizes[0] / 128;
    int n_edges = in_sizes[1];

    void *pWh_v, *pH1_v, *pCnt_v, *pOff_v, *pCur_v, *pCsr_v;
    cudaGetSymbolAddress(&pWh_v,  g_Wh);
    cudaGetSymbolAddress(&pH1_v,  g_h1);
    cudaGetSymbolAddress(&pCnt_v, g_cnt);
    cudaGetSymbolAddress(&pOff_v, g_off);
    cudaGetSymbolAddress(&pCur_v, g_cursor);
    cudaGetSymbolAddress(&pCsr_v, g_csr);
    float* pWh  = (float*)pWh_v;
    float* pH1  = (float*)pH1_v;
    int*   pCnt = (int*)pCnt_v;
    int*   pOff = (int*)pOff_v;
    int*   pCur = (int*)pCur_v;
    int2*  pCsr = (int2*)pCsr_v;

    int eb = (n_edges + 255) / 256;
    int gemm_blocks = (n_nodes + TILE_M - 1) / TILE_M;
    int agg_blocks = (n_nodes * 16 + 255) / 256;

    // CSR build (shared by both layers)
    cudaMemsetAsync(pCnt, 0, (size_t)n_nodes * sizeof(int));
    hist_kernel<<<eb, 256>>>(dst, pCnt, n_edges);
    scan_kernel<<<1, SCAN_T>>>(pCnt, pOff, pCur, n_nodes);
    fill_kernel<<<eb, 256>>>(src, dst, ew, pCur, pCsr, n_edges);

    // Layer 1
    gemm_tile_kernel<128><<<gemm_blocks, 128>>>(x, W1, b1, pWh, n_nodes);
    aggregate_kernel<true><<<agg_blocks, 256>>>(
        (const float4*)pWh, pCsr, pOff, pH1, n_nodes);

    // Layer 2
    gemm_tile_kernel<64><<<gemm_blocks, 128>>>(pH1, W2, b2, pWh, n_nodes);
    aggregate_kernel<false><<<agg_blocks, 256>>>(
        (const float4*)pWh, pCsr, pOff, out, n_nodes);
}

// round 5
// speedup vs baseline: 1.1358x; 1.1358x over previous
#include <cuda_runtime.h>
#include <cuda_bf16.h>
#include <cstdint>

// ---------------------------------------------------------------------------
// WordGraphNet: 2-layer weighted GraphConv, CSR pull-side aggregation.
//   layer(h,W,b): Wh = h@W + b ; s = segsum(Wh[src]*ew, dst) ; out = s/max(deg,1)
//   out = layer2( leaky_relu(layer1(x)) )
// ---------------------------------------------------------------------------

#define MAX_NODES 50000
#define MAX_EDGES 1200000
#define HID 64
#define NEG_SLOPE 0.01f
#define SCAN_T 1024

typedef unsigned long long ull;

__device__ float g_Wh[MAX_NODES * HID];
__device__ float g_h1[MAX_NODES * HID];
__device__ int   g_cnt[MAX_NODES];
__device__ int   g_off[MAX_NODES + 1];
__device__ int   g_cursor[MAX_NODES];
__device__ int2  g_csr[MAX_EDGES];

__device__ __forceinline__ float leaky(float v) {
    return v > 0.f ? v : NEG_SLOPE * v;
}

// ---- packed f32x2 helpers (Blackwell FFMA2) ----
__device__ __forceinline__ ull pack2dup(float v) {
    ull r; asm("mov.b64 %0, {%1, %1};" : "=l"(r) : "f"(v)); return r;
}
__device__ __forceinline__ void unpack2(ull v, float& lo, float& hi) {
    asm("mov.b64 {%0, %1}, %2;" : "=f"(lo), "=f"(hi) : "l"(v));
}
__device__ __forceinline__ ull fma2(ull a, ull b, ull c) {
    ull d; asm("fma.rn.f32x2 %0, %1, %2, %3;" : "=l"(d) : "l"(a), "l"(b), "l"(c));
    return d;
}

// ---------------------------------------------------------------------------
// CSR build
// ---------------------------------------------------------------------------
__global__ void hist_kernel(const int* __restrict__ dst, int* __restrict__ cnt,
                            int n_edges) {
    int e = blockIdx.x * blockDim.x + threadIdx.x;
    if (e < n_edges) atomicAdd(cnt + __ldg(dst + e), 1);
}

__global__ __launch_bounds__(SCAN_T)
void scan_kernel(const int* __restrict__ cnt, int* __restrict__ off,
                 int* __restrict__ cursor, int n) {
    __shared__ int sums[SCAN_T];
    int t = threadIdx.x;
    int ch = (n + SCAN_T - 1) / SCAN_T;
    int begin = min(t * ch, n);
    int end   = min(begin + ch, n);

    int s = 0;
    for (int i = begin; i < end; i++) s += __ldg(cnt + i);
    sums[t] = s;
    __syncthreads();

    for (int d = 1; d < SCAN_T; d <<= 1) {
        int v = (t >= d) ? sums[t - d] : 0;
        __syncthreads();
        sums[t] += v;
        __syncthreads();
    }

    int run = (t == 0) ? 0 : sums[t - 1];
    for (int i = begin; i < end; i++) {
        off[i] = run;
        cursor[i] = run;
        run += __ldg(cnt + i);
    }
    if (t == SCAN_T - 1) off[n] = sums[SCAN_T - 1];
}

__global__ void fill_kernel(const int* __restrict__ src, const int* __restrict__ dst,
                            const float* __restrict__ ew, int* __restrict__ cursor,
                            int2* __restrict__ csr, int n_edges) {
    int e = blockIdx.x * blockDim.x + threadIdx.x;
    if (e >= n_edges) return;
    int d = __ldg(dst + e);
    int pos = atomicAdd(cursor + d, 1);
    csr[pos] = make_int2(__ldg(src + e), __float_as_int(__ldg(ew + e)));
}

// ---------------------------------------------------------------------------
// Tiled GEMM + bias, f32x2 inner product.
// 128 threads, tile 128 nodes x 64 cols, 8 nodes x 8 cols per thread.
// ---------------------------------------------------------------------------
#define TILE_M 128
#define KC 32
#define KCP 36

template <int K>
__global__ __launch_bounds__(128)
void gemm_tile_kernel(const float* __restrict__ H,
                      const float* __restrict__ Wg,
                      const float* __restrict__ bg,
                      float* __restrict__ out,
                      int n_nodes) {
    __shared__ float Hs[TILE_M * KCP];
    __shared__ float Ws[KC * HID];

    const int tid = threadIdx.x;
    const int tx = tid & 7;
    const int ty = tid >> 3;
    const int node0 = blockIdx.x * TILE_M;

    ull acc2[8][4];
#pragma unroll
    for (int i = 0; i < 8; i++)
#pragma unroll
        for (int j = 0; j < 4; j++) acc2[i][j] = 0ull;

    for (int kc0 = 0; kc0 < K; kc0 += KC) {
        {
            const float4* Wg4 = reinterpret_cast<const float4*>(Wg + kc0 * HID);
            float4* Ws4w = reinterpret_cast<float4*>(Ws);
#pragma unroll
            for (int f = tid; f < KC * 16; f += 128)
                Ws4w[f] = __ldg(Wg4 + f);
        }
#pragma unroll
        for (int f = tid; f < TILE_M * (KC / 4); f += 128) {
            int m = f >> 3;
            int j = f & 7;
            int node = node0 + m;
            float4 v = make_float4(0.f, 0.f, 0.f, 0.f);
            if (node < n_nodes)
                v = __ldg(reinterpret_cast<const float4*>(H + (size_t)node * K + kc0) + j);
            *reinterpret_cast<float4*>(Hs + m * KCP + 4 * j) = v;
        }
        __syncthreads();

        const ull* Ws2 = reinterpret_cast<const ull*>(Ws);
#pragma unroll 4
        for (int kk = 0; kk < KC; kk++) {
            ull w2[4];
            w2[0] = Ws2[kk * 32 + 2 * tx];
            w2[1] = Ws2[kk * 32 + 2 * tx + 1];
            w2[2] = Ws2[kk * 32 + 16 + 2 * tx];
            w2[3] = Ws2[kk * 32 + 16 + 2 * tx + 1];
#pragma unroll
            for (int i = 0; i < 8; i++) {
                ull h2 = pack2dup(Hs[(ty + 16 * i) * KCP + kk]);
#pragma unroll
                for (int j = 0; j < 4; j++)
                    acc2[i][j] = fma2(h2, w2[j], acc2[i][j]);
            }
        }
        __syncthreads();
    }

    float4 b0 = __ldg(reinterpret_cast<const float4*>(bg) + tx);
    float4 b1 = __ldg(reinterpret_cast<const float4*>(bg) + 8 + tx);
#pragma unroll
    for (int i = 0; i < 8; i++) {
        int node = node0 + ty + 16 * i;
        if (node < n_nodes) {
            float4 o0, o1;
            unpack2(acc2[i][0], o0.x, o0.y);
            unpack2(acc2[i][1], o0.z, o0.w);
            unpack2(acc2[i][2], o1.x, o1.y);
            unpack2(acc2[i][3], o1.z, o1.w);
            o0.x += b0.x; o0.y += b0.y; o0.z += b0.z; o0.w += b0.w;
            o1.x += b1.x; o1.y += b1.y; o1.z += b1.z; o1.w += b1.w;
            *reinterpret_cast<float4*>(out + (size_t)node * HID + tx * 4) = o0;
            *reinterpret_cast<float4*>(out + (size_t)node * HID + 32 + tx * 4) = o1;
        }
    }
}

// ---------------------------------------------------------------------------
// Pull-side aggregate, register-batched (MLP=8), branchless tail.
// 16 lanes per node; lane c4 owns float4 chunk c4 of the 64-wide row.
// Each round: 8 csr entries -> registers (independent LDG.64, warp-broadcast),
// then 8 independent gathers, then FMAs. Tail: index clamped to end-1 (same
// cache line => no extra traffic), weight zeroed.
// ---------------------------------------------------------------------------
template <bool DO_LEAKY>
__global__ __launch_bounds__(256)
void aggregate_kernel(const float4* __restrict__ Wh4,
                      const int2* __restrict__ csr,
                      const int* __restrict__ off,
                      float* __restrict__ out,
                      int n_nodes) {
    int gid = blockIdx.x * blockDim.x + threadIdx.x;
    int node = gid >> 4;
    int c4 = gid & 15;
    if (node >= n_nodes) return;

    int e   = __ldg(off + node);
    int end = __ldg(off + node + 1);
    float deg = (float)(end - e);

    float4 acc = make_float4(0.f, 0.f, 0.f, 0.f);

    for (; e < end; e += 8) {
        int2 c[8];
#pragma unroll
        for (int j = 0; j < 8; j++)
            c[j] = __ldg(csr + min(e + j, end - 1));

        float4 v[8];
#pragma unroll
        for (int j = 0; j < 8; j++)
            v[j] = __ldg(Wh4 + (size_t)c[j].x * 16 + c4);

#pragma unroll
        for (int j = 0; j < 8; j++) {
            float w = (e + j < end) ? __int_as_float(c[j].y) : 0.f;
            acc.x += v[j].x * w;
            acc.y += v[j].y * w;
            acc.z += v[j].z * w;
            acc.w += v[j].w * w;
        }
    }

    float inv = 1.0f / fmaxf(deg, 1.0f);
    acc.x *= inv; acc.y *= inv; acc.z *= inv; acc.w *= inv;
    if (DO_LEAKY) {
        acc.x = leaky(acc.x); acc.y = leaky(acc.y);
        acc.z = leaky(acc.z); acc.w = leaky(acc.w);
    }
    reinterpret_cast<float4*>(out)[gid] = acc;
}

// ---------------------------------------------------------------------------
// Launch
// ---------------------------------------------------------------------------
extern "C" void kernel_launch(void* const* d_in, const int* in_sizes, int n_in,
                              void* d_out, int out_size) {
    const float* x   = (const float*)d_in[0];
    const float* ew  = (const float*)d_in[1];
    const float* W1  = (const float*)d_in[2];
    const float* b1  = (const float*)d_in[3];
    const float* W2  = (const float*)d_in[4];
    const float* b2  = (const float*)d_in[5];
    const int*   src = (const int*)d_in[6];
    const int*   dst = (const int*)d_in[7];
    float*       out = (float*)d_out;

    int n_nodes = in_sizes[0] / 128;
    int n_edges = in_sizes[1];

    void *pWh_v, *pH1_v, *pCnt_v, *pOff_v, *pCur_v, *pCsr_v;
    cudaGetSymbolAddress(&pWh_v,  g_Wh);
    cudaGetSymbolAddress(&pH1_v,  g_h1);
    cudaGetSymbolAddress(&pCnt_v, g_cnt);
    cudaGetSymbolAddress(&pOff_v, g_off);
    cudaGetSymbolAddress(&pCur_v, g_cursor);
    cudaGetSymbolAddress(&pCsr_v, g_csr);
    float* pWh  = (float*)pWh_v;
    float* pH1  = (float*)pH1_v;
    int*   pCnt = (int*)pCnt_v;
    int*   pOff = (int*)pOff_v;
    int*   pCur = (int*)pCur_v;
    int2*  pCsr = (int2*)pCsr_v;

    int eb = (n_edges + 255) / 256;
    int gemm_blocks = (n_nodes + TILE_M - 1) / TILE_M;
    int agg_blocks = (n_nodes * 16 + 255) / 256;

    // CSR build (shared by both layers)
    cudaMemsetAsync(pCnt, 0, (size_t)n_nodes * sizeof(int));
    hist_kernel<<<eb, 256>>>(dst, pCnt, n_edges);
    scan_kernel<<<1, SCAN_T>>>(pCnt, pOff, pCur, n_nodes);
    fill_kernel<<<eb, 256>>>(src, dst, ew, pCur, pCsr, n_edges);

    // Layer 1
    gemm_tile_kernel<128><<<gemm_blocks, 128>>>(x, W1, b1, pWh, n_nodes);
    aggregate_kernel<true><<<agg_blocks, 256>>>(
        (const float4*)pWh, pCsr, pOff, pH1, n_nodes);

    // Layer 2
    gemm_tile_kernel<64><<<gemm_blocks, 128>>>(pH1, W2, b2, pWh, n_nodes);
    aggregate_kernel<false><<<agg_blocks, 256>>>(
        (const float4*)pWh, pCsr, pOff, out, n_nodes);
}

// round 6
// speedup vs baseline: 1.6883x; 1.4864x over previous
#include <cuda_runtime.h>
#include <cuda_bf16.h>
#include <cstdint>

// ---------------------------------------------------------------------------
// WordGraphNet: 2-layer weighted GraphConv, CSR pull-side aggregation.
//   layer(h,W,b): Wh = h@W + b ; s = segsum(Wh[src]*ew, dst) ; out = s/max(deg,1)
//   out = layer2( leaky_relu(layer1(x)) )
// ---------------------------------------------------------------------------

#define MAX_NODES 50000
#define MAX_EDGES 1200000
#define HID 64
#define NEG_SLOPE 0.01f

// multi-block scan config: 256 threads x 8 items = 2048 entries per block
#define SB_T 256
#define SB_I 8
#define SB_CHUNK (SB_T * SB_I)
#define MAX_SCAN_BLOCKS ((MAX_NODES + SB_CHUNK - 1) / SB_CHUNK)

typedef unsigned long long ull;

__device__ float g_Wh[MAX_NODES * HID];
__device__ float g_h1[MAX_NODES * HID];
__device__ int   g_cnt[MAX_NODES];
__device__ int   g_off[MAX_NODES + 1];
__device__ int   g_cursor[MAX_NODES];
__device__ int   g_bsum[MAX_SCAN_BLOCKS];
__device__ int2  g_csr[MAX_EDGES];

__device__ __forceinline__ float leaky(float v) {
    return v > 0.f ? v : NEG_SLOPE * v;
}

// ---- packed f32x2 helpers (Blackwell FFMA2) ----
__device__ __forceinline__ ull pack2dup(float v) {
    ull r; asm("mov.b64 %0, {%1, %1};" : "=l"(r) : "f"(v)); return r;
}
__device__ __forceinline__ void unpack2(ull v, float& lo, float& hi) {
    asm("mov.b64 {%0, %1}, %2;" : "=f"(lo), "=f"(hi) : "l"(v));
}
__device__ __forceinline__ ull fma2(ull a, ull b, ull c) {
    ull d; asm("fma.rn.f32x2 %0, %1, %2, %3;" : "=l"(d) : "l"(a), "l"(b), "l"(c));
    return d;
}

// ---------------------------------------------------------------------------
// CSR build: hist -> 3-phase multi-block exclusive scan -> fill
// ---------------------------------------------------------------------------
__global__ void hist_kernel(const int* __restrict__ dst, int* __restrict__ cnt,
                            int n_edges) {
    int e = blockIdx.x * blockDim.x + threadIdx.x;
    if (e < n_edges) atomicAdd(cnt + __ldg(dst + e), 1);
}

// Phase 1: per-block totals (coalesced strided reduce)
__global__ __launch_bounds__(SB_T)
void partial_sum_kernel(const int* __restrict__ cnt, int* __restrict__ bsum, int n) {
    __shared__ int red[SB_T];
    int base = blockIdx.x * SB_CHUNK;
    int t = threadIdx.x;
    int s = 0;
#pragma unroll
    for (int k = 0; k < SB_I; k++) {
        int i = base + k * SB_T + t;
        if (i < n) s += __ldg(cnt + i);
    }
    red[t] = s;
    __syncthreads();
    for (int d = SB_T / 2; d > 0; d >>= 1) {
        if (t < d) red[t] += red[t + d];
        __syncthreads();
    }
    if (t == 0) bsum[blockIdx.x] = red[0];
}

// Phase 2: single-warp exclusive scan of block totals; writes off[n] = total.
__global__ void scan_bsum_kernel(int* __restrict__ bsum, int* __restrict__ off,
                                 int nb, int n) {
    int t = threadIdx.x;  // 32 threads, nb <= 32
    int v = (t < nb) ? bsum[t] : 0;
    int incl = v;
#pragma unroll
    for (int d = 1; d < 32; d <<= 1) {
        int o = __shfl_up_sync(0xffffffffu, incl, d);
        if (t >= d) incl += o;
    }
    if (t < nb) bsum[t] = incl - v;              // exclusive base per block
    if (t == 31) off[n] = incl;                  // grand total
}

// Phase 3: per-block prefix write of off + cursor.
__global__ __launch_bounds__(SB_T)
void write_off_kernel(const int* __restrict__ cnt, const int* __restrict__ bsum,
                      int* __restrict__ off, int* __restrict__ cursor, int n) {
    __shared__ int ts[SB_T];
    int base = blockIdx.x * SB_CHUNK;
    int t = threadIdx.x;

    int c[SB_I];
    int s = 0;
#pragma unroll
    for (int k = 0; k < SB_I; k++) {
        int i = base + t * SB_I + k;
        c[k] = (i < n) ? __ldg(cnt + i) : 0;
        s += c[k];
    }
    ts[t] = s;
    __syncthreads();
    // Hillis-Steele inclusive scan over thread sums
    for (int d = 1; d < SB_T; d <<= 1) {
        int v = (t >= d) ? ts[t - d] : 0;
        __syncthreads();
        ts[t] += v;
        __syncthreads();
    }
    int run = __ldg(bsum + blockIdx.x) + ((t == 0) ? 0 : ts[t - 1]);
#pragma unroll
    for (int k = 0; k < SB_I; k++) {
        int i = base + t * SB_I + k;
        if (i < n) {
            off[i] = run;
            cursor[i] = run;
            run += c[k];
        }
    }
}

__global__ void fill_kernel(const int* __restrict__ src, const int* __restrict__ dst,
                            const float* __restrict__ ew, int* __restrict__ cursor,
                            int2* __restrict__ csr, int n_edges) {
    int e = blockIdx.x * blockDim.x + threadIdx.x;
    if (e >= n_edges) return;
    int d = __ldg(dst + e);
    int pos = atomicAdd(cursor + d, 1);
    csr[pos] = make_int2(__ldg(src + e), __float_as_int(__ldg(ew + e)));
}

// ---------------------------------------------------------------------------
// Tiled GEMM + bias, f32x2 inner product. (unchanged from round 5)
// ---------------------------------------------------------------------------
#define TILE_M 128
#define KC 32
#define KCP 36

template <int K>
__global__ __launch_bounds__(128)
void gemm_tile_kernel(const float* __restrict__ H,
                      const float* __restrict__ Wg,
                      const float* __restrict__ bg,
                      float* __restrict__ out,
                      int n_nodes) {
    __shared__ float Hs[TILE_M * KCP];
    __shared__ float Ws[KC * HID];

    const int tid = threadIdx.x;
    const int tx = tid & 7;
    const int ty = tid >> 3;
    const int node0 = blockIdx.x * TILE_M;

    ull acc2[8][4];
#pragma unroll
    for (int i = 0; i < 8; i++)
#pragma unroll
        for (int j = 0; j < 4; j++) acc2[i][j] = 0ull;

    for (int kc0 = 0; kc0 < K; kc0 += KC) {
        {
            const float4* Wg4 = reinterpret_cast<const float4*>(Wg + kc0 * HID);
            float4* Ws4w = reinterpret_cast<float4*>(Ws);
#pragma unroll
            for (int f = tid; f < KC * 16; f += 128)
                Ws4w[f] = __ldg(Wg4 + f);
        }
#pragma unroll
        for (int f = tid; f < TILE_M * (KC / 4); f += 128) {
            int m = f >> 3;
            int j = f & 7;
            int node = node0 + m;
            float4 v = make_float4(0.f, 0.f, 0.f, 0.f);
            if (node < n_nodes)
                v = __ldg(reinterpret_cast<const float4*>(H + (size_t)node * K + kc0) + j);
            *reinterpret_cast<float4*>(Hs + m * KCP + 4 * j) = v;
        }
        __syncthreads();

        const ull* Ws2 = reinterpret_cast<const ull*>(Ws);
#pragma unroll 4
        for (int kk = 0; kk < KC; kk++) {
            ull w2[4];
            w2[0] = Ws2[kk * 32 + 2 * tx];
            w2[1] = Ws2[kk * 32 + 2 * tx + 1];
            w2[2] = Ws2[kk * 32 + 16 + 2 * tx];
            w2[3] = Ws2[kk * 32 + 16 + 2 * tx + 1];
#pragma unroll
            for (int i = 0; i < 8; i++) {
                ull h2 = pack2dup(Hs[(ty + 16 * i) * KCP + kk]);
#pragma unroll
                for (int j = 0; j < 4; j++)
                    acc2[i][j] = fma2(h2, w2[j], acc2[i][j]);
            }
        }
        __syncthreads();
    }

    float4 b0 = __ldg(reinterpret_cast<const float4*>(bg) + tx);
    float4 b1 = __ldg(reinterpret_cast<const float4*>(bg) + 8 + tx);
#pragma unroll
    for (int i = 0; i < 8; i++) {
        int node = node0 + ty + 16 * i;
        if (node < n_nodes) {
            float4 o0, o1;
            unpack2(acc2[i][0], o0.x, o0.y);
            unpack2(acc2[i][1], o0.z, o0.w);
            unpack2(acc2[i][2], o1.x, o1.y);
            unpack2(acc2[i][3], o1.z, o1.w);
            o0.x += b0.x; o0.y += b0.y; o0.z += b0.z; o0.w += b0.w;
            o1.x += b1.x; o1.y += b1.y; o1.z += b1.z; o1.w += b1.w;
            *reinterpret_cast<float4*>(out + (size_t)node * HID + tx * 4) = o0;
            *reinterpret_cast<float4*>(out + (size_t)node * HID + 32 + tx * 4) = o1;
        }
    }
}

// ---------------------------------------------------------------------------
// Pull-side aggregate, register-batched (MLP=8), branchless tail.
// (unchanged from round 5)
// ---------------------------------------------------------------------------
template <bool DO_LEAKY>
__global__ __launch_bounds__(256)
void aggregate_kernel(const float4* __restrict__ Wh4,
                      const int2* __restrict__ csr,
                      const int* __restrict__ off,
                      float* __restrict__ out,
                      int n_nodes) {
    int gid = blockIdx.x * blockDim.x + threadIdx.x;
    int node = gid >> 4;
    int c4 = gid & 15;
    if (node >= n_nodes) return;

    int e   = __ldg(off + node);
    int end = __ldg(off + node + 1);
    float deg = (float)(end - e);

    float4 acc = make_float4(0.f, 0.f, 0.f, 0.f);

    for (; e < end; e += 8) {
        int2 c[8];
#pragma unroll
        for (int j = 0; j < 8; j++)
            c[j] = __ldg(csr + min(e + j, end - 1));

        float4 v[8];
#pragma unroll
        for (int j = 0; j < 8; j++)
            v[j] = __ldg(Wh4 + (size_t)c[j].x * 16 + c4);

#pragma unroll
        for (int j = 0; j < 8; j++) {
            float w = (e + j < end) ? __int_as_float(c[j].y) : 0.f;
            acc.x += v[j].x * w;
            acc.y += v[j].y * w;
            acc.z += v[j].z * w;
            acc.w += v[j].w * w;
        }
    }

    float inv = 1.0f / fmaxf(deg, 1.0f);
    acc.x *= inv; acc.y *= inv; acc.z *= inv; acc.w *= inv;
    if (DO_LEAKY) {
        acc.x = leaky(acc.x); acc.y = leaky(acc.y);
        acc.z = leaky(acc.z); acc.w = leaky(acc.w);
    }
    reinterpret_cast<float4*>(out)[gid] = acc;
}

// ---------------------------------------------------------------------------
// Launch
// ---------------------------------------------------------------------------
extern "C" void kernel_launch(void* const* d_in, const int* in_sizes, int n_in,
                              void* d_out, int out_size) {
    const float* x   = (const float*)d_in[0];
    const float* ew  = (const float*)d_in[1];
    const float* W1  = (const float*)d_in[2];
    const float* b1  = (const float*)d_in[3];
    const float* W2  = (const float*)d_in[4];
    const float* b2  = (const float*)d_in[5];
    const int*   src = (const int*)d_in[6];
    const int*   dst = (const int*)d_in[7];
    float*       out = (float*)d_out;

    int n_nodes = in_sizes[0] / 128;
    int n_edges = in_sizes[1];

    void *pWh_v, *pH1_v, *pCnt_v, *pOff_v, *pCur_v, *pCsr_v, *pBs_v;
    cudaGetSymbolAddress(&pWh_v,  g_Wh);
    cudaGetSymbolAddress(&pH1_v,  g_h1);
    cudaGetSymbolAddress(&pCnt_v, g_cnt);
    cudaGetSymbolAddress(&pOff_v, g_off);
    cudaGetSymbolAddress(&pCur_v, g_cursor);
    cudaGetSymbolAddress(&pCsr_v, g_csr);
    cudaGetSymbolAddress(&pBs_v,  g_bsum);
    float* pWh  = (float*)pWh_v;
    float* pH1  = (float*)pH1_v;
    int*   pCnt = (int*)pCnt_v;
    int*   pOff = (int*)pOff_v;
    int*   pCur = (int*)pCur_v;
    int2*  pCsr = (int2*)pCsr_v;
    int*   pBs  = (int*)pBs_v;

    int eb = (n_edges + 255) / 256;
    int gemm_blocks = (n_nodes + TILE_M - 1) / TILE_M;
    int agg_blocks = (n_nodes * 16 + 255) / 256;
    int scan_blocks = (n_nodes + SB_CHUNK - 1) / SB_CHUNK;

    // CSR build (shared by both layers)
    cudaMemsetAsync(pCnt, 0, (size_t)n_nodes * sizeof(int));
    hist_kernel<<<eb, 256>>>(dst, pCnt, n_edges);
    partial_sum_kernel<<<scan_blocks, SB_T>>>(pCnt, pBs, n_nodes);
    scan_bsum_kernel<<<1, 32>>>(pBs, pOff, scan_blocks, n_nodes);
    write_off_kernel<<<scan_blocks, SB_T>>>(pCnt, pBs, pOff, pCur, n_nodes);
    fill_kernel<<<eb, 256>>>(src, dst, ew, pCur, pCsr, n_edges);

    // Layer 1
    gemm_tile_kernel<128><<<gemm_blocks, 128>>>(x, W1, b1, pWh, n_nodes);
    aggregate_kernel<true><<<agg_blocks, 256>>>(
        (const float4*)pWh, pCsr, pOff, pH1, n_nodes);

    // Layer 2
    gemm_tile_kernel<64><<<gemm_blocks, 128>>>(pH1, W2, b2, pWh, n_nodes);
    aggregate_kernel<false><<<agg_blocks, 256>>>(
        (const float4*)pWh, pCsr, pOff, out, n_nodes);
}

// round 7
// speedup vs baseline: 1.7777x; 1.0529x over previous
#include <cuda_runtime.h>
#include <cuda_fp16.h>
#include <cstdint>

// ---------------------------------------------------------------------------
// WordGraphNet: 2-layer weighted GraphConv, CSR pull-side aggregation.
//   layer(h,W,b): Wh = h@W + b ; s = segsum(Wh[src]*ew, dst) ; out = s/max(deg,1)
//   out = layer2( leaky_relu(layer1(x)) )
// Wh stored fp16 (gather traffic halved); all arithmetic fp32.
// ---------------------------------------------------------------------------

#define MAX_NODES 50000
#define MAX_EDGES 1200000
#define HID 64
#define NEG_SLOPE 0.01f

#define SB_T 256
#define SB_I 8
#define SB_CHUNK (SB_T * SB_I)
#define MAX_SCAN_BLOCKS ((MAX_NODES + SB_CHUNK - 1) / SB_CHUNK)

typedef unsigned long long ull;

__device__ __half g_Wh[MAX_NODES * HID];      // projected features (fp16)
__device__ float  g_h1[MAX_NODES * HID];      // layer-1 output (fp32)
__device__ int    g_cnt[MAX_NODES];
__device__ int    g_off[MAX_NODES + 1];
__device__ int    g_cursor[MAX_NODES];
__device__ int    g_bsum[MAX_SCAN_BLOCKS];
__device__ int2   g_csr[MAX_EDGES];

__device__ __forceinline__ float leaky(float v) {
    return v > 0.f ? v : NEG_SLOPE * v;
}

// ---- packed f32x2 helpers (Blackwell FFMA2) ----
__device__ __forceinline__ ull pack2dup(float v) {
    ull r; asm("mov.b64 %0, {%1, %1};" : "=l"(r) : "f"(v)); return r;
}
__device__ __forceinline__ void unpack2(ull v, float& lo, float& hi) {
    asm("mov.b64 {%0, %1}, %2;" : "=f"(lo), "=f"(hi) : "l"(v));
}
__device__ __forceinline__ ull fma2(ull a, ull b, ull c) {
    ull d; asm("fma.rn.f32x2 %0, %1, %2, %3;" : "=l"(d) : "l"(a), "l"(b), "l"(c));
    return d;
}

// ---------------------------------------------------------------------------
// CSR build: hist -> 3-phase multi-block exclusive scan -> fill
// ---------------------------------------------------------------------------
__global__ void hist_kernel(const int* __restrict__ dst, int* __restrict__ cnt,
                            int n_edges) {
    int e = blockIdx.x * blockDim.x + threadIdx.x;
    if (e < n_edges) atomicAdd(cnt + __ldg(dst + e), 1);
}

__global__ __launch_bounds__(SB_T)
void partial_sum_kernel(const int* __restrict__ cnt, int* __restrict__ bsum, int n) {
    __shared__ int red[SB_T];
    int base = blockIdx.x * SB_CHUNK;
    int t = threadIdx.x;
    int s = 0;
#pragma unroll
    for (int k = 0; k < SB_I; k++) {
        int i = base + k * SB_T + t;
        if (i < n) s += __ldg(cnt + i);
    }
    red[t] = s;
    __syncthreads();
    for (int d = SB_T / 2; d > 0; d >>= 1) {
        if (t < d) red[t] += red[t + d];
        __syncthreads();
    }
    if (t == 0) bsum[blockIdx.x] = red[0];
}

__global__ void scan_bsum_kernel(int* __restrict__ bsum, int* __restrict__ off,
                                 int nb, int n) {
    int t = threadIdx.x;  // 32 threads, nb <= 32
    int v = (t < nb) ? bsum[t] : 0;
    int incl = v;
#pragma unroll
    for (int d = 1; d < 32; d <<= 1) {
        int o = __shfl_up_sync(0xffffffffu, incl, d);
        if (t >= d) incl += o;
    }
    if (t < nb) bsum[t] = incl - v;
    if (t == 31) off[n] = incl;
}

__global__ __launch_bounds__(SB_T)
void write_off_kernel(const int* __restrict__ cnt, const int* __restrict__ bsum,
                      int* __restrict__ off, int* __restrict__ cursor, int n) {
    __shared__ int ts[SB_T];
    int base = blockIdx.x * SB_CHUNK;
    int t = threadIdx.x;

    int c[SB_I];
    int s = 0;
#pragma unroll
    for (int k = 0; k < SB_I; k++) {
        int i = base + t * SB_I + k;
        c[k] = (i < n) ? __ldg(cnt + i) : 0;
        s += c[k];
    }
    ts[t] = s;
    __syncthreads();
    for (int d = 1; d < SB_T; d <<= 1) {
        int v = (t >= d) ? ts[t - d] : 0;
        __syncthreads();
        ts[t] += v;
        __syncthreads();
    }
    int run = __ldg(bsum + blockIdx.x) + ((t == 0) ? 0 : ts[t - 1]);
#pragma unroll
    for (int k = 0; k < SB_I; k++) {
        int i = base + t * SB_I + k;
        if (i < n) {
            off[i] = run;
            cursor[i] = run;
            run += c[k];
        }
    }
}

__global__ void fill_kernel(const int* __restrict__ src, const int* __restrict__ dst,
                            const float* __restrict__ ew, int* __restrict__ cursor,
                            int2* __restrict__ csr, int n_edges) {
    int e = blockIdx.x * blockDim.x + threadIdx.x;
    if (e >= n_edges) return;
    int d = __ldg(dst + e);
    int pos = atomicAdd(cursor + d, 1);
    csr[pos] = make_int2(__ldg(src + e), __float_as_int(__ldg(ew + e)));
}

// ---------------------------------------------------------------------------
// Tiled GEMM + bias, f32x2 inner product, fp16 output.
// 128 threads, tile 128 nodes x 64 cols, 8 nodes x 8 cols per thread.
// ---------------------------------------------------------------------------
#define TILE_M 128
#define KC 32
#define KCP 36

template <int K>
__global__ __launch_bounds__(128)
void gemm_tile_kernel(const float* __restrict__ H,
                      const float* __restrict__ Wg,
                      const float* __restrict__ bg,
                      __half* __restrict__ out,
                      int n_nodes) {
    __shared__ float Hs[TILE_M * KCP];
    __shared__ float Ws[KC * HID];

    const int tid = threadIdx.x;
    const int tx = tid & 7;
    const int ty = tid >> 3;
    const int node0 = blockIdx.x * TILE_M;

    ull acc2[8][4];
#pragma unroll
    for (int i = 0; i < 8; i++)
#pragma unroll
        for (int j = 0; j < 4; j++) acc2[i][j] = 0ull;

    for (int kc0 = 0; kc0 < K; kc0 += KC) {
        {
            const float4* Wg4 = reinterpret_cast<const float4*>(Wg + kc0 * HID);
            float4* Ws4w = reinterpret_cast<float4*>(Ws);
#pragma unroll
            for (int f = tid; f < KC * 16; f += 128)
                Ws4w[f] = __ldg(Wg4 + f);
        }
#pragma unroll
        for (int f = tid; f < TILE_M * (KC / 4); f += 128) {
            int m = f >> 3;
            int j = f & 7;
            int node = node0 + m;
            float4 v = make_float4(0.f, 0.f, 0.f, 0.f);
            if (node < n_nodes)
                v = __ldg(reinterpret_cast<const float4*>(H + (size_t)node * K + kc0) + j);
            *reinterpret_cast<float4*>(Hs + m * KCP + 4 * j) = v;
        }
        __syncthreads();

        const ull* Ws2 = reinterpret_cast<const ull*>(Ws);
#pragma unroll 4
        for (int kk = 0; kk < KC; kk++) {
            ull w2[4];
            w2[0] = Ws2[kk * 32 + 2 * tx];
            w2[1] = Ws2[kk * 32 + 2 * tx + 1];
            w2[2] = Ws2[kk * 32 + 16 + 2 * tx];
            w2[3] = Ws2[kk * 32 + 16 + 2 * tx + 1];
#pragma unroll
            for (int i = 0; i < 8; i++) {
                ull h2 = pack2dup(Hs[(ty + 16 * i) * KCP + kk]);
#pragma unroll
                for (int j = 0; j < 4; j++)
                    acc2[i][j] = fma2(h2, w2[j], acc2[i][j]);
            }
        }
        __syncthreads();
    }

    float4 b0 = __ldg(reinterpret_cast<const float4*>(bg) + tx);
    float4 b1 = __ldg(reinterpret_cast<const float4*>(bg) + 8 + tx);
#pragma unroll
    for (int i = 0; i < 8; i++) {
        int node = node0 + ty + 16 * i;
        if (node < n_nodes) {
            float4 o0, o1;
            unpack2(acc2[i][0], o0.x, o0.y);
            unpack2(acc2[i][1], o0.z, o0.w);
            unpack2(acc2[i][2], o1.x, o1.y);
            unpack2(acc2[i][3], o1.z, o1.w);
            o0.x += b0.x; o0.y += b0.y; o0.z += b0.z; o0.w += b0.w;
            o1.x += b1.x; o1.y += b1.y; o1.z += b1.z; o1.w += b1.w;
            __half2 h00 = __floats2half2_rn(o0.x, o0.y);
            __half2 h01 = __floats2half2_rn(o0.z, o0.w);
            __half2 h10 = __floats2half2_rn(o1.x, o1.y);
            __half2 h11 = __floats2half2_rn(o1.z, o1.w);
            __half2* orow = reinterpret_cast<__half2*>(out + (size_t)node * HID);
            orow[2 * tx]          = h00;
            orow[2 * tx + 1]      = h01;
            orow[16 + 2 * tx]     = h10;
            orow[16 + 2 * tx + 1] = h11;
        }
    }
}

// ---------------------------------------------------------------------------
// Pull-side aggregate, register-batched (MLP=8), branchless tail.
// 16 lanes per node; lane c4 owns 4 output floats = 4 fp16 gathers (uint2).
// ---------------------------------------------------------------------------
template <bool DO_LEAKY>
__global__ __launch_bounds__(256)
void aggregate_kernel(const uint2* __restrict__ Whh,
                      const int2* __restrict__ csr,
                      const int* __restrict__ off,
                      float* __restrict__ out,
                      int n_nodes) {
    int gid = blockIdx.x * blockDim.x + threadIdx.x;
    int node = gid >> 4;
    int c4 = gid & 15;
    if (node >= n_nodes) return;

    int e   = __ldg(off + node);
    int end = __ldg(off + node + 1);
    float deg = (float)(end - e);

    float4 acc = make_float4(0.f, 0.f, 0.f, 0.f);

    for (; e < end; e += 8) {
        int2 c[8];
#pragma unroll
        for (int j = 0; j < 8; j++)
            c[j] = __ldg(csr + min(e + j, end - 1));

        uint2 v[8];
#pragma unroll
        for (int j = 0; j < 8; j++)
            v[j] = __ldg(Whh + (size_t)c[j].x * 16 + c4);

#pragma unroll
        for (int j = 0; j < 8; j++) {
            float w = (e + j < end) ? __int_as_float(c[j].y) : 0.f;
            float2 lo = __half22float2(*reinterpret_cast<__half2*>(&v[j].x));
            float2 hi = __half22float2(*reinterpret_cast<__half2*>(&v[j].y));
            acc.x += lo.x * w;
            acc.y += lo.y * w;
            acc.z += hi.x * w;
            acc.w += hi.y * w;
        }
    }

    float inv = 1.0f / fmaxf(deg, 1.0f);
    acc.x *= inv; acc.y *= inv; acc.z *= inv; acc.w *= inv;
    if (DO_LEAKY) {
        acc.x = leaky(acc.x); acc.y = leaky(acc.y);
        acc.z = leaky(acc.z); acc.w = leaky(acc.w);
    }
    reinterpret_cast<float4*>(out)[gid] = acc;
}

// ---------------------------------------------------------------------------
// Launch
// ---------------------------------------------------------------------------
extern "C" void kernel_launch(void* const* d_in, const int* in_sizes, int n_in,
                              void* d_out, int out_size) {
    const float* x   = (const float*)d_in[0];
    const float* ew  = (const float*)d_in[1];
    const float* W1  = (const float*)d_in[2];
    const float* b1  = (const float*)d_in[3];
    const float* W2  = (const float*)d_in[4];
    const float* b2  = (const float*)d_in[5];
    const int*   src = (const int*)d_in[6];
    const int*   dst = (const int*)d_in[7];
    float*       out = (float*)d_out;

    int n_nodes = in_sizes[0] / 128;
    int n_edges = in_sizes[1];

    void *pWh_v, *pH1_v, *pCnt_v, *pOff_v, *pCur_v, *pCsr_v, *pBs_v;
    cudaGetSymbolAddress(&pWh_v,  g_Wh);
    cudaGetSymbolAddress(&pH1_v,  g_h1);
    cudaGetSymbolAddress(&pCnt_v, g_cnt);
    cudaGetSymbolAddress(&pOff_v, g_off);
    cudaGetSymbolAddress(&pCur_v, g_cursor);
    cudaGetSymbolAddress(&pCsr_v, g_csr);
    cudaGetSymbolAddress(&pBs_v,  g_bsum);
    __half* pWh = (__half*)pWh_v;
    float*  pH1 = (float*)pH1_v;
    int*    pCnt = (int*)pCnt_v;
    int*    pOff = (int*)pOff_v;
    int*    pCur = (int*)pCur_v;
    int2*   pCsr = (int2*)pCsr_v;
    int*    pBs  = (int*)pBs_v;

    int eb = (n_edges + 255) / 256;
    int gemm_blocks = (n_nodes + TILE_M - 1) / TILE_M;
    int agg_blocks = (n_nodes * 16 + 255) / 256;
    int scan_blocks = (n_nodes + SB_CHUNK - 1) / SB_CHUNK;

    // CSR build (shared by both layers)
    cudaMemsetAsync(pCnt, 0, (size_t)n_nodes * sizeof(int));
    hist_kernel<<<eb, 256>>>(dst, pCnt, n_edges);
    partial_sum_kernel<<<scan_blocks, SB_T>>>(pCnt, pBs, n_nodes);
    scan_bsum_kernel<<<1, 32>>>(pBs, pOff, scan_blocks, n_nodes);
    write_off_kernel<<<scan_blocks, SB_T>>>(pCnt, pBs, pOff, pCur, n_nodes);
    fill_kernel<<<eb, 256>>>(src, dst, ew, pCur, pCsr, n_edges);

    // Layer 1
    gemm_tile_kernel<128><<<gemm_blocks, 128>>>(x, W1, b1, pWh, n_nodes);
    aggregate_kernel<true><<<agg_blocks, 256>>>(
        (const uint2*)pWh, pCsr, pOff, pH1, n_nodes);

    // Layer 2
    gemm_tile_kernel<64><<<gemm_blocks, 128>>>(pH1, W2, b2, pWh, n_nodes);
    aggregate_kernel<false><<<agg_blocks, 256>>>(
        (const uint2*)pWh, pCsr, pOff, out, n_nodes);
}